// round 17
// baseline (speedup 1.0000x reference)
#include <cuda_runtime.h>
#include <cuda_bf16.h>
#include <stdint.h>

#define LATENT 512
#define MCODES 1024
#define ROWS_CTA 128
#define NT 512

// ---------------- device scratch (no allocs allowed) ----------------
__device__ __nv_bfloat16 g_cb16[MCODES * LATENT];  // bf16 codebook (1MB, L2-resident)
__device__ float g_b2[MCODES];                     // codebook row sumsq (fp32)

// ---------------- smem layout (dynamic) ----------------
#define SM_A2    0                      // 128 floats -> 512
#define SM_B2    512                    // 1024 floats -> 4608
#define SM_RV    4608                   // 128*4 floats -> 6656
#define SM_MINV  6656                   // 128 floats -> 7168
#define SM_CNT   7168                   // 16 ints -> 7232
#define SM_CLIST 7232                   // 16*16 ints -> 8256
#define SM_A     9216                   // 128x512 bf16 swizzled (128KB), 1KB-aligned
#define SM_B     140288                 // 3 buffers x 16KB (128 codes x 64 k each)
#define SM_TOTAL 189440                 // ~185KB -> 1 CTA/SM

__device__ __forceinline__ uint32_t su32(const void* p) {
    uint32_t a;
    asm("{ .reg .u64 t; cvta.to.shared.u64 t, %1; cvt.u32.u64 %0, t; }" : "=r"(a) : "l"(p));
    return a;
}

// A tile (128 rows x 512 k): 8-row x 64-bf16 atoms (1KB); k-group stride 16KB.
__device__ __forceinline__ uint32_t toffA(int row, int k) {
    return (uint32_t)((row >> 3) * 1024 + (k >> 6) * 16384 + (row & 7) * 128 + (k & 63) * 2);
}
// B chunk (128 rows x 64 k): 8-row x 64-bf16 atoms, single k-group (16KB).
__device__ __forceinline__ uint32_t toffB(int row, int k) {
    return (uint32_t)((row >> 3) * 1024 + (row & 7) * 128 + (k & 63) * 2);
}
__device__ __forceinline__ uint32_t swz(uint32_t o) { return o ^ ((o >> 3) & 0x70); }

__device__ __forceinline__ void cp16(uint32_t dst, const void* src) {
    asm volatile("cp.async.cg.shared.global [%0], [%1], 16;" :: "r"(dst), "l"(src) : "memory");
}

__device__ __forceinline__ void ldsm4(uint32_t addr, uint32_t& r0, uint32_t& r1,
                                      uint32_t& r2, uint32_t& r3) {
    asm volatile("ldmatrix.sync.aligned.m8n8.x4.shared.b16 {%0,%1,%2,%3}, [%4];"
                 : "=r"(r0), "=r"(r1), "=r"(r2), "=r"(r3) : "r"(addr));
}

__device__ __forceinline__ void mma16816(float* d, uint32_t a0, uint32_t a1, uint32_t a2,
                                         uint32_t a3, uint32_t b0, uint32_t b1) {
    asm volatile(
        "mma.sync.aligned.m16n8k16.row.col.f32.bf16.bf16.f32 "
        "{%0,%1,%2,%3}, {%4,%5,%6,%7}, {%8,%9}, {%0,%1,%2,%3};"
        : "+f"(d[0]), "+f"(d[1]), "+f"(d[2]), "+f"(d[3])
        : "r"(a0), "r"(a1), "r"(a2), "r"(a3), "r"(b0), "r"(b1));
}

// ---------------- prep: bf16 codebook + b2 ----------------
__global__ void prep_kernel(const float* __restrict__ C) {
    int warp = (blockIdx.x * blockDim.x + threadIdx.x) >> 5;
    int lane = threadIdx.x & 31;
    if (warp >= MCODES) return;
    const float4* row = (const float4*)(C + (size_t)warp * LATENT);
    uint2* out = (uint2*)(g_cb16 + (size_t)warp * LATENT);
    float s = 0.f;
#pragma unroll
    for (int i = 0; i < 4; i++) {
        float4 v = row[lane + i * 32];
        s += v.x * v.x + v.y * v.y + v.z * v.z + v.w * v.w;
        __nv_bfloat162 p0 = __float22bfloat162_rn(make_float2(v.x, v.y));
        __nv_bfloat162 p1 = __float22bfloat162_rn(make_float2(v.z, v.w));
        uint2 pk;
        pk.x = *(uint32_t*)&p0;
        pk.y = *(uint32_t*)&p1;
        out[lane + i * 32] = pk;
    }
#pragma unroll
    for (int o = 16; o > 0; o >>= 1) s += __shfl_xor_sync(~0u, s, o);
    if (!lane) g_b2[warp] = s;
}

// ---------------- main fused VQ kernel (128 rows/CTA, 3-stage pipeline) --------
__global__ void __launch_bounds__(NT, 1)
vq_kernel(const float* __restrict__ X, const float* __restrict__ C,
          float* __restrict__ quant, float* __restrict__ dist)
{
    extern __shared__ char smem[];
    const uint32_t sb = su32(smem);
    const int t = threadIdx.x;
    const int lane = t & 31;
    const int warp = t >> 5;
    const int wm = warp >> 2;          // 0..3: rows wm*32..+31
    const int wn = warp & 3;           // 0..3: cols wn*32..+31 (within 128-col tile)
    const int rowBase = blockIdx.x * ROWS_CTA;

    float* a2s = (float*)(smem + SM_A2);
    float* b2s = (float*)(smem + SM_B2);

    // ---- load A (128x512) fp32 -> bf16 swizzled smem; fused a2 ----
    {
        int row = t >> 2;              // 0..127
        int kb = (t & 3) * 128;
        const float4* src = (const float4*)(X + (size_t)(rowBase + row) * LATENT + kb);
        float s = 0.f;
#pragma unroll 4
        for (int i = 0; i < 16; i++) {
            float4 a = src[2 * i];
            float4 b = src[2 * i + 1];
            s += a.x * a.x + a.y * a.y + a.z * a.z + a.w * a.w;
            s += b.x * b.x + b.y * b.y + b.z * b.z + b.w * b.w;
            int k = kb + i * 8;
            __nv_bfloat162 q0 = __float22bfloat162_rn(make_float2(a.x, a.y));
            __nv_bfloat162 q1 = __float22bfloat162_rn(make_float2(a.z, a.w));
            __nv_bfloat162 q2 = __float22bfloat162_rn(make_float2(b.x, b.y));
            __nv_bfloat162 q3 = __float22bfloat162_rn(make_float2(b.z, b.w));
            uint4 pk;
            pk.x = *(uint32_t*)&q0; pk.y = *(uint32_t*)&q1;
            pk.z = *(uint32_t*)&q2; pk.w = *(uint32_t*)&q3;
            *(uint4*)(smem + SM_A + swz(toffA(row, k))) = pk;
        }
        s += __shfl_xor_sync(~0u, s, 1);
        s += __shfl_xor_sync(~0u, s, 2);
        if (!(t & 3)) a2s[row] = s;
    }
    for (int i = t; i < MCODES; i += NT) b2s[i] = g_b2[i];
    __syncthreads();

    // ldmatrix lane geometry (x4: matrices at lanes 0-7,8-15,16-23,24-31)
    const int mat = lane >> 3;
    const int arow = wm * 32 + (lane & 7) + ((mat & 1) ? 8 : 0);
    const int akd  = (mat & 2) ? 8 : 0;
    const int brow = (lane & 7) + ((mat & 2) ? 8 : 0);
    const int bkd  = (mat & 1) ? 8 : 0;

    // Hoisted swizzled B offsets (buffer bases are 16KB-aligned rel. SM_B,
    // never touching swizzle source bits 7-9).
    uint32_t bOf0[4], bOf1[4];
#pragma unroll
    for (int ks = 0; ks < 4; ks++) {
        bOf0[ks] = swz(toffB(wn * 32 + brow,      ks * 16 + bkd));
        bOf1[ks] = swz(toffB(wn * 32 + 16 + brow, ks * 16 + bkd));
    }

    const int g = lane >> 2;           // fragment row group
    float my_a2[4];
#pragma unroll
    for (int s = 0; s < 4; s++)
        my_a2[s] = a2s[wm * 32 + (s >> 1) * 16 + (s & 1) * 8 + g];

    float acc[2][4][4];
#pragma unroll
    for (int mt = 0; mt < 2; mt++)
#pragma unroll
        for (int nn = 0; nn < 4; nn++)
#pragma unroll
            for (int e = 0; e < 4; e++) acc[mt][nn][e] = 0.f;

    float bestv[4];
#pragma unroll
    for (int s = 0; s < 4; s++) bestv[s] = 3.4e38f;

    // ---- B chunk loader: gl = nt*8 + kc; chunk = 128 codes x 64 k (16KB) ----
    // 3 buffers at SM_B + (gl%3)*16384.
    auto loadB = [&](int gl) {
        int nt = gl >> 3, kc = gl & 7;
        uint32_t dstb = sb + SM_B + (uint32_t)(gl % 3) * 16384u;
        const __nv_bfloat16* src = g_cb16 + (size_t)(nt * 128) * LATENT + kc * 64;
#pragma unroll
        for (int j = 0; j < 2; j++) {
            int unit = t + j * NT;         // 0..1023
            int row = unit >> 3;           // 0..127
            int k = (unit & 7) * 8;        // 0..56
            cp16(dstb + swz(toffB(row, k)), src + (size_t)row * LATENT + k);
        }
        asm volatile("cp.async.commit_group;" ::: "memory");
    };

    loadB(0);
    loadB(1);

    int gl = 0;
#pragma unroll 1
    for (int nt = 0; nt < 8; nt++) {
#pragma unroll 1
        for (int kc = 0; kc < 8; kc++) {
            if (gl < 63) asm volatile("cp.async.wait_group 1;" ::: "memory");
            else         asm volatile("cp.async.wait_group 0;" ::: "memory");
            __syncthreads();               // single barrier per chunk (3-stage)

            const uint32_t aB = sb + SM_A;
            const uint32_t bB = sb + SM_B + (uint32_t)(gl % 3) * 16384u;
#pragma unroll
            for (int ks = 0; ks < 4; ks++) {
                const int ak = kc * 64 + ks * 16 + akd;
                uint32_t a0[4], a1[4];
                ldsm4(aB + swz(toffA(arow,      ak)), a0[0], a0[1], a0[2], a0[3]);
                ldsm4(aB + swz(toffA(arow + 16, ak)), a1[0], a1[1], a1[2], a1[3]);
                uint32_t bf[4][2];
                ldsm4(bB + bOf0[ks], bf[0][0], bf[0][1], bf[1][0], bf[1][1]);
                ldsm4(bB + bOf1[ks], bf[2][0], bf[2][1], bf[3][0], bf[3][1]);
#pragma unroll
                for (int nn = 0; nn < 4; nn++) {
                    mma16816(acc[0][nn], a0[0], a0[1], a0[2], a0[3], bf[nn][0], bf[nn][1]);
                    mma16816(acc[1][nn], a1[0], a1[1], a1[2], a1[3], bf[nn][0], bf[nn][1]);
                }
            }
            // No post-compute barrier: buffer (gl+2)%3 was last READ at iter gl-1,
            // and every warp passed this iter's top barrier only after finishing it.
            if (gl + 2 < 64) loadB(gl + 2);
            gl++;
        }

        // ---- epilogue for this 128-col tile: distances, dist stores, min track ----
        const int colbase = nt * 128 + wn * 32;
#pragma unroll
        for (int mt = 0; mt < 2; mt++) {
            const int rA = wm * 32 + mt * 16 + g;
            const int rB = rA + 8;
            const float a2A = my_a2[mt * 2];
            const float a2B = my_a2[mt * 2 + 1];
            float* dA = dist + (size_t)(rowBase + rA) * MCODES;
            float* dB = dist + (size_t)(rowBase + rB) * MCODES;
#pragma unroll
            for (int nn = 0; nn < 4; nn++) {
                const int c0 = colbase + nn * 8 + (lane & 3) * 2;
                const float2 b2p = *(const float2*)&b2s[c0];
                float d0 = fmaf(-2.f, acc[mt][nn][0], a2A + b2p.x);
                float d1 = fmaf(-2.f, acc[mt][nn][1], a2A + b2p.y);
                float d2 = fmaf(-2.f, acc[mt][nn][2], a2B + b2p.x);
                float d3 = fmaf(-2.f, acc[mt][nn][3], a2B + b2p.y);
                bestv[mt * 2]     = fminf(bestv[mt * 2],     fminf(d0, d1));
                bestv[mt * 2 + 1] = fminf(bestv[mt * 2 + 1], fminf(d2, d3));
                *(float2*)(dA + c0) = make_float2(d0, d1);
                *(float2*)(dB + c0) = make_float2(d2, d3);
                acc[mt][nn][0] = 0.f; acc[mt][nn][1] = 0.f;
                acc[mt][nn][2] = 0.f; acc[mt][nn][3] = 0.f;
            }
        }
    }

    // ---- per-row bf16-level min value ----
    float* rv = (float*)(smem + SM_RV);
    float* minvS = (float*)(smem + SM_MINV);
#pragma unroll
    for (int s = 0; s < 4; s++) {
        float v = bestv[s];
        v = fminf(v, __shfl_xor_sync(~0u, v, 1));
        v = fminf(v, __shfl_xor_sync(~0u, v, 2));
        if ((lane & 3) == 0) {
            int row = wm * 32 + (s >> 1) * 16 + (s & 1) * 8 + g;
            rv[row * 4 + wn] = v;
        }
    }
    __syncthreads();
    if (t < ROWS_CTA)
        minvS[t] = fminf(fminf(rv[t * 4], rv[t * 4 + 1]),
                         fminf(rv[t * 4 + 2], rv[t * 4 + 3]));
    __syncthreads();

    // ================= PHASE 2: exact fp32 rescore of candidates =================
    int* cnt = (int*)(smem + SM_CNT);
    int* clist = (int*)(smem + SM_CLIST) + warp * 16;

    for (int r = warp; r < ROWS_CTA; r += 16) {
        if (!lane) cnt[warp] = 0;
        __syncwarp();
        const float thr = minvS[r] + 0.25f;
        const float4* drow4 = (const float4*)(dist + (size_t)(rowBase + r) * MCODES);
#pragma unroll
        for (int j = 0; j < 8; j++) {
            float4 v = drow4[lane + 32 * j];
            int base = (lane + 32 * j) * 4;
            if (v.x <= thr) { int p = atomicAdd(&cnt[warp], 1); if (p < 16) clist[p] = base; }
            if (v.y <= thr) { int p = atomicAdd(&cnt[warp], 1); if (p < 16) clist[p] = base + 1; }
            if (v.z <= thr) { int p = atomicAdd(&cnt[warp], 1); if (p < 16) clist[p] = base + 2; }
            if (v.w <= thr) { int p = atomicAdd(&cnt[warp], 1); if (p < 16) clist[p] = base + 3; }
        }
        __syncwarp();
        int m = cnt[warp];
        if (m > 16) m = 16;

        const float4* xr = (const float4*)(X + (size_t)(rowBase + r) * LATENT);
        float4 xv[4];
#pragma unroll
        for (int q = 0; q < 4; q++) xv[q] = xr[lane + 32 * q];
        const float a2r = a2s[r];

        float bs = 3.4e38f;
        int bi = 0x7fffffff;
        for (int ci = 0; ci < m; ci++) {
            int c = clist[ci];
            const float4* cr = (const float4*)(C + (size_t)c * LATENT);
            float s = 0.f;
#pragma unroll
            for (int q = 0; q < 4; q++) {
                float4 cv = cr[lane + 32 * q];
                s += xv[q].x * cv.x + xv[q].y * cv.y + xv[q].z * cv.z + xv[q].w * cv.w;
            }
#pragma unroll
            for (int o = 16; o > 0; o >>= 1) s += __shfl_xor_sync(~0u, s, o);
            float sc = (a2r - 2.f * s) + b2s[c];
            if (sc < bs || (sc == bs && c < bi)) { bs = sc; bi = c; }
        }

        const float4* src = (const float4*)(C + (size_t)bi * LATENT);
        float4* dst = (float4*)(quant + (size_t)(rowBase + r) * LATENT);
#pragma unroll
        for (int q = 0; q < 4; q++) dst[lane + 32 * q] = src[lane + 32 * q];
    }
}

extern "C" void kernel_launch(void* const* d_in, const int* in_sizes, int n_in,
                              void* d_out, int out_size) {
    const float* X = (const float*)d_in[0];
    const float* C = (const float*)d_in[1];
    const int n = in_sizes[0] / LATENT;              // 65536
    float* quant = (float*)d_out;                    // (n, 512)
    float* dist  = (float*)d_out + (size_t)n * LATENT;

    prep_kernel<<<(MCODES * 32) / 256, 256>>>(C);

    cudaFuncSetAttribute(vq_kernel, cudaFuncAttributeMaxDynamicSharedMemorySize, SM_TOTAL);
    vq_kernel<<<n / ROWS_CTA, NT, SM_TOTAL>>>(X, C, quant, dist);
}